// round 11
// baseline (speedup 1.0000x reference)
#include <cuda_runtime.h>
#include <cuda_fp16.h>
#include <math.h>
#include <stdint.h>

// Problem constants
#define Bq   8
#define Cc   256
#define Hh   64
#define Ww   64
#define Nn   4096            // H*W
#define NH   4
#define HD   64
#define BN   (Bq*Nn)         // 32768

// ---------------- scratch (device globals; no allocation allowed) -------------
__device__ __half g_xn_h[BN*Cc];     // layernormed x (fp16 rounded), [b*N+n][c]
__device__ __half g_wB_h[768*Cc];    // folded qkv weight [o][c], fp16 hi
__device__ __half g_wB_l[768*Cc];    // fp16 lo residual
__device__ __half g_wP_h[Cc*Cc];     // proj weight transposed [o][c], fp16 (rounded)
__device__ __half g_qh[Bq*Cc*Nn];    // q fp16 (rounded), row = bh*64+d, col n
__device__ __half g_kh[Bq*Cc*Nn];    // k fp16 hi
__device__ __half g_kl[Bq*Cc*Nn];    // k fp16 lo
__device__ __half g_v   [Bq*Cc*Nn];  // v fp16, (B,C,N) head-major
__device__ __half g_att [Bq*Cc*Nn];  // attened_x fp16, (B,C,N)
__device__ __half g_conv[Bq*Cc*Nn];  // gelu(dwconv) fp16, (B,C,N)
__device__ float g_attn[Bq*NH*HD*HD];  // raw logits q@k^T, (B,nh,hd,hd)
__device__ float g_pool[Bq*Cc];        // sum over n of attened
__device__ float g_gc  [Bq*Cc];        // sigmoid(channel_map)
__device__ float g_gs  [Bq*Nn];        // sigmoid(spatial_map)
__device__ float g_sqq [Bq*Cc];        // sum of squares per q row
__device__ float g_sqk [Bq*Cc];

__device__ __forceinline__ float gelu_f(float x){
    return 0.5f * x * (1.0f + erff(x * 0.70710678118654752f));
}
__device__ __forceinline__ float sigmoid_f(float x){
    return 1.0f / (1.0f + expf(-x));
}
__device__ __forceinline__ uint32_t smem_u32(const void* p){
    uint32_t a;
    asm("{ .reg .u64 t; cvta.to.shared.u64 t, %1; cvt.u32.u64 %0, t; }" : "=r"(a) : "l"(p));
    return a;
}
__device__ __forceinline__ void ldmx4(uint32_t* r, uint32_t addr){
    asm volatile("ldmatrix.sync.aligned.m8n8.x4.shared.b16 {%0,%1,%2,%3}, [%4];"
                 : "=r"(r[0]), "=r"(r[1]), "=r"(r[2]), "=r"(r[3]) : "r"(addr));
}
__device__ __forceinline__ void ldmx4t(uint32_t* r, uint32_t addr){
    asm volatile("ldmatrix.sync.aligned.m8n8.x4.trans.shared.b16 {%0,%1,%2,%3}, [%4];"
                 : "=r"(r[0]), "=r"(r[1]), "=r"(r[2]), "=r"(r[3]) : "r"(addr));
}
__device__ __forceinline__ void mma_f16(float* d, const uint32_t* a, uint32_t b0, uint32_t b1){
    asm volatile(
        "mma.sync.aligned.m16n8k16.row.col.f32.f16.f16.f32 "
        "{%0,%1,%2,%3}, {%4,%5,%6,%7}, {%8,%9}, {%0,%1,%2,%3};"
        : "+f"(d[0]), "+f"(d[1]), "+f"(d[2]), "+f"(d[3])
        : "r"(a[0]), "r"(a[1]), "r"(a[2]), "r"(a[3]), "r"(b0), "r"(b1));
}
__device__ __forceinline__ void cpa16(uint32_t d, const void* s){
    asm volatile("cp.async.cg.shared.global [%0], [%1], 16;" :: "r"(d), "l"(s));
}
__device__ __forceinline__ uint32_t pack_h2(__half a, __half b){
    return ((uint32_t)__half_as_ushort(b) << 16) | (uint32_t)__half_as_ushort(a);
}
__device__ __forceinline__ void split_h(float v, __half& h, __half& l){
    h = __float2half(v);
    l = __float2half(v - __half2float(h));
}

// qkv pipeline smem: k-chunk 32 fp16 = 64B rows padded to 80B; 3 arrays/stage, 3 stages
#define QT    80
#define QSTG  30720
#define QAH   0
#define QAL   10240
#define QBH   20480
#define QKV_SMEM 92160

// ---------------- 0: zero the accumulated buffers -----------------------------
__global__ void k_zero(){
    int i = blockIdx.x * 256 + threadIdx.x;
    if (i < Bq*NH*HD*HD) g_attn[i] = 0.f;
    if (i < Bq*Cc){ g_pool[i] = 0.f; g_sqq[i] = 0.f; g_sqk[i] = 0.f; }
}

// ---------------- 1: LayerNorm over C -> g_xn_h fp16, layout [b*N+n][c] --------
__global__ void k_layernorm(const float* __restrict__ x,
                            const float* __restrict__ g,
                            const float* __restrict__ b){
    __shared__ float sx[256][33];
    __shared__ float spart[8][32];
    __shared__ float smu[32], sinv[32];
    int bb = blockIdx.x >> 7;
    int n0 = (blockIdx.x & 127) * 32;
    int tid = threadIdx.x;
    int nl = tid & 31, part = tid >> 5;
    const float* xb = x + (size_t)bb * Cc * Nn + n0;
    #pragma unroll
    for (int c0 = 0; c0 < 256; c0 += 8)
        sx[c0 + part][nl] = xb[(size_t)(c0 + part) * Nn + nl];
    __syncthreads();
    float s = 0.f, s2 = 0.f;
    #pragma unroll
    for (int i = 0; i < 32; i++){ float v = sx[part*32 + i][nl]; s += v; s2 += v*v; }
    spart[part][nl] = s;
    __syncthreads();
    if (part == 0){ float t = 0.f; for (int p = 0; p < 8; p++) t += spart[p][nl]; smu[nl] = t * (1.f/256.f); }
    __syncthreads();
    spart[part][nl] = s2;
    __syncthreads();
    if (part == 0){
        float t = 0.f; for (int p = 0; p < 8; p++) t += spart[p][nl];
        float mu = smu[nl];
        sinv[nl] = rsqrtf(t * (1.f/256.f) - mu*mu + 1e-5f);
    }
    __syncthreads();
    float gc = g[tid], bc = b[tid];
    for (int n = 0; n < 32; n++){
        float val = (sx[tid][n] - smu[n]) * sinv[n] * gc + bc;
        g_xn_h[((size_t)(bb * Nn) + n0 + n) * 256 + tid] = __float2half(val);
    }
}

// ---------------- 2: merged weight prep: buildW (blocks 0..255) + buildP -------
__global__ void k_buildWP(const float* __restrict__ wqkv, const float* __restrict__ wq,
                          const float* __restrict__ wp){
    int blk = blockIdx.x;
    int tid = threadIdx.x;
    if (blk < 256){
        __shared__ float srow[768];
        __shared__ float swq[64*64];
        int c = blk;
        for (int i = tid; i < 768; i += 256)  srow[i] = wqkv[(size_t)c*768 + i];
        for (int i = tid; i < 4096; i += 256) swq[i]  = wq[i];
        __syncthreads();
        int h = tid >> 6, d = tid & 63;
        float s = 0.f;
        #pragma unroll 16
        for (int e = 0; e < 64; e++) s += srow[h*64 + e] * swq[e*64 + d];
        float vals[3] = { s, srow[256 + tid], srow[512 + tid] };
        #pragma unroll
        for (int t = 0; t < 3; t++){
            int o = t*256 + tid;
            __half hi, lo; split_h(vals[t], hi, lo);
            g_wB_h[(size_t)o*256 + c] = hi;
            g_wB_l[(size_t)o*256 + c] = lo;
        }
    } else {
        __shared__ float t[32][33];
        int bp = blk - 256;
        int tx = tid & 31, ty = tid >> 5;   // 32 x 8
        int c0 = (bp & 7) * 32, o0 = (bp >> 3) * 32;
        #pragma unroll
        for (int r = 0; r < 32; r += 8)
            t[ty + r][tx] = wp[(size_t)(c0 + ty + r) * 256 + o0 + tx];
        __syncthreads();
        #pragma unroll
        for (int r = 0; r < 32; r += 8)
            g_wP_h[(size_t)(o0 + ty + r) * 256 + c0 + tx] = __float2half(t[tx][ty + r]);
    }
}

// ---------------- 3: qkv GEMM via mma.sync fp16x2, 3-stage, 1 sync/chunk -------
#define QKV_ISSUE(kc_) do{ \
    uint32_t d_ = drow + ((kc_) % 3) * QSTG; \
    size_t go_ = (size_t)(kc_) * 64; \
    cpa16(d_ + QAH,      pwh + go_);      cpa16(d_ + QAH + 16, pwh + go_ + 16); \
    cpa16(d_ + QAL,      pwl + go_);      cpa16(d_ + QAL + 16, pwl + go_ + 16); \
    cpa16(d_ + QBH,      pxh + go_);      cpa16(d_ + QBH + 16, pxh + go_ + 16); \
    asm volatile("cp.async.commit_group;"); } while(0)

__global__ void __launch_bounds__(256, 2) k_qkv_mma(const float* __restrict__ bq){
    extern __shared__ char dsm[];
    uint32_t sb = smem_u32(dsm);
    int tid = threadIdx.x, wid = tid >> 5, lid = tid & 31;
    int warp_m = wid >> 2, warp_n = wid & 3;
    int cblk = blockIdx.x * 128;
    int bn0  = blockIdx.y * 128;
    int bb = bn0 >> 12, n0 = bn0 & (Nn-1);

    int gr = tid >> 1, ghf = tid & 1;
    const char* pwh = (const char*)(g_wB_h + (size_t)(cblk + gr)*256) + ghf*32;
    const char* pwl = (const char*)(g_wB_l + (size_t)(cblk + gr)*256) + ghf*32;
    const char* pxh = (const char*)(g_xn_h + (size_t)(bn0  + gr)*256) + ghf*32;
    uint32_t drow = sb + gr*QT + ghf*32;

    QKV_ISSUE(0);
    QKV_ISSUE(1);

    uint32_t aAo = (uint32_t)((warp_m*64 + (lid & 7) + ((lid >> 3) & 1)*8)*QT + ((lid >> 4) & 1)*16);
    uint32_t aBo = (uint32_t)((warp_n*32 + (lid & 7) + ((lid >> 4) & 1)*8)*QT + ((lid >> 3) & 1)*16);

    float acc[4][4][4] = {};

    #pragma unroll 1
    for (int kc = 0; kc < 8; kc++){
        if (kc < 7) asm volatile("cp.async.wait_group 1;");
        else        asm volatile("cp.async.wait_group 0;");
        __syncthreads();
        if (kc < 6) QKV_ISSUE(kc + 2);
        uint32_t base = sb + (kc % 3)*QSTG;
        #pragma unroll
        for (int ks = 0; ks < 2; ks++){
            uint32_t kofs = ks*32;
            uint32_t bh[8], arh[4], arl[4];
            ldmx4(bh,     base + QBH + aBo + kofs);
            ldmx4(bh + 4, base + QBH + aBo + kofs + 16*QT);
            #pragma unroll
            for (int mi = 0; mi < 4; mi++){
                ldmx4(arh, base + QAH + aAo + kofs + (uint32_t)(mi*16)*QT);
                ldmx4(arl, base + QAL + aAo + kofs + (uint32_t)(mi*16)*QT);
                #pragma unroll
                for (int ni = 0; ni < 4; ni++) mma_f16(acc[mi][ni], arh, bh[ni*2], bh[ni*2+1]);
                #pragma unroll
                for (int ni = 0; ni < 4; ni++) mma_f16(acc[mi][ni], arl, bh[ni*2], bh[ni*2+1]);
            }
        }
    }

    // epilogue: q -> fp16 (+norms), k -> fp16 hi/lo (+norms), v -> fp16
    int gid = lid >> 2, q4 = lid & 3;
    int obase = cblk + warp_m*64 + gid;
    int ot = obase >> 8;                 // 0=q,1=k,2=v (constant per block)
    #pragma unroll
    for (int mi = 0; mi < 4; mi++){
        int o0 = obase + mi*16;
        float bo0 = (ot == 0) ? bq[o0 & 63] : 0.f;
        float bo1 = (ot == 0) ? bq[(o0 + 8) & 63] : 0.f;
        size_t row0 = ((size_t)(bb*Cc + (o0 & 255))) * Nn;
        size_t row1 = ((size_t)(bb*Cc + ((o0 + 8) & 255))) * Nn;
        float s0 = 0.f, s1 = 0.f;
        #pragma unroll
        for (int ni = 0; ni < 4; ni++){
            int n = n0 + warp_n*32 + ni*8 + q4*2;
            float v0 = acc[mi][ni][0] + bo0, v1 = acc[mi][ni][1] + bo0;
            float v2 = acc[mi][ni][2] + bo1, v3 = acc[mi][ni][3] + bo1;
            if (ot == 2){
                *(uint32_t*)&g_v[row0 + n] = pack_h2(__float2half(v0), __float2half(v1));
                *(uint32_t*)&g_v[row1 + n] = pack_h2(__float2half(v2), __float2half(v3));
            } else if (ot == 0){
                *(uint32_t*)&g_qh[row0 + n] = pack_h2(__float2half(v0), __float2half(v1));
                *(uint32_t*)&g_qh[row1 + n] = pack_h2(__float2half(v2), __float2half(v3));
                s0 += v0*v0 + v1*v1;
                s1 += v2*v2 + v3*v3;
            } else {
                __half h0,l0,h1,l1,h2,l2,h3,l3;
                split_h(v0,h0,l0); split_h(v1,h1,l1);
                split_h(v2,h2,l2); split_h(v3,h3,l3);
                *(uint32_t*)&g_kh[row0 + n] = pack_h2(h0, h1);
                *(uint32_t*)&g_kl[row0 + n] = pack_h2(l0, l1);
                *(uint32_t*)&g_kh[row1 + n] = pack_h2(h2, h3);
                *(uint32_t*)&g_kl[row1 + n] = pack_h2(l2, l3);
                s0 += v0*v0 + v1*v1;
                s1 += v2*v2 + v3*v3;
            }
        }
        if (ot < 2){
            s0 += __shfl_xor_sync(0xFFFFFFFF, s0, 1);
            s0 += __shfl_xor_sync(0xFFFFFFFF, s0, 2);
            s1 += __shfl_xor_sync(0xFFFFFFFF, s1, 1);
            s1 += __shfl_xor_sync(0xFFFFFFFF, s1, 2);
            if (q4 == 0){
                float* sq = ot ? g_sqk : g_sqq;
                atomicAdd(&sq[bb*Cc + (o0 & 255)], s0);
                atomicAdd(&sq[bb*Cc + ((o0 + 8) & 255)], s1);
            }
        }
    }
}

// ---------------- 4: attn logits = q @ k^T, cp.async 2-stage --------------------
#define AQT   144   // 72 fp16 row stride (bytes)
#define AQSTG 27648 // 3 arrays x 64 x 144
__global__ void __launch_bounds__(256) k_attn_qk_mma(){
    __shared__ __align__(16) char sm[2*AQSTG];
    uint32_t sb = smem_u32(sm);
    const int OQH = 0, OKH = 64*AQT, OKL = 2*64*AQT;
    int tid = threadIdx.x, wid = tid >> 5, lid = tid & 31;
    int warp_m = wid >> 1, warp_n = wid & 1;
    int bh = blockIdx.y;
    int nbase = blockIdx.x * 512;

    int r_ = tid >> 2, c16_ = (tid & 3)*2;   // 2 chunks of 16B per thread
    size_t gbase = ((size_t)(bh*64 + r_))*Nn;
    uint32_t sobase = r_*AQT + c16_*16;

    #define AQ_ISSUE(kc_) do{ \
        uint32_t st_ = sb + ((kc_) & 1)*AQSTG + sobase; \
        size_t g_ = gbase + (size_t)(nbase + (kc_)*64) + c16_*8; \
        cpa16(st_ + OQH,      g_qh + g_);  cpa16(st_ + OQH + 16, g_qh + g_ + 8); \
        cpa16(st_ + OKH,      g_kh + g_);  cpa16(st_ + OKH + 16, g_kh + g_ + 8); \
        cpa16(st_ + OKL,      g_kl + g_);  cpa16(st_ + OKL + 16, g_kl + g_ + 8); \
        asm volatile("cp.async.commit_group;"); } while(0)

    AQ_ISSUE(0);

    uint32_t aAo = (uint32_t)((warp_m*16 + (lid & 7) + ((lid >> 3) & 1)*8)*AQT + ((lid >> 4) & 1)*16);
    uint32_t aBo = (uint32_t)((warp_n*32 + (lid & 7) + ((lid >> 4) & 1)*8)*AQT + ((lid >> 3) & 1)*16);

    float acc[4][4] = {};

    #pragma unroll 1
    for (int kc = 0; kc < 8; kc++){
        asm volatile("cp.async.wait_group 0;");
        __syncthreads();
        if (kc < 7) AQ_ISSUE(kc + 1);
        uint32_t base = sb + (kc & 1)*AQSTG;
        #pragma unroll
        for (int ks = 0; ks < 4; ks++){
            uint32_t kofs = ks*32;
            uint32_t bh_[8], bl_[8], arh[4];
            ldmx4(bh_,     base + OKH + aBo + kofs);
            ldmx4(bh_ + 4, base + OKH + aBo + kofs + 16*AQT);
            ldmx4(bl_,     base + OKL + aBo + kofs);
            ldmx4(bl_ + 4, base + OKL + aBo + kofs + 16*AQT);
            ldmx4(arh, base + OQH + aAo + kofs);
            #pragma unroll
            for (int ni = 0; ni < 4; ni++) mma_f16(acc[ni], arh, bh_[ni*2], bh_[ni*2+1]);
            #pragma unroll
            for (int ni = 0; ni < 4; ni++) mma_f16(acc[ni], arh, bl_[ni*2], bl_[ni*2+1]);
        }
        __syncthreads();
    }

    int gid = lid >> 2, q4 = lid & 3;
    float* dst = g_attn + (size_t)bh*HD*HD;
    #pragma unroll
    for (int ni = 0; ni < 4; ni++){
        int e = warp_n*32 + ni*8 + q4*2;
        int d0 = warp_m*16 + gid;
        atomicAdd(&dst[d0*64 + e],     acc[ni][0]);
        atomicAdd(&dst[d0*64 + e + 1], acc[ni][1]);
        atomicAdd(&dst[(d0+8)*64 + e],     acc[ni][2]);
        atomicAdd(&dst[(d0+8)*64 + e + 1], acc[ni][3]);
    }
}

// ---------------- 5: attened = softmax(attn) @ v, fused softmax + pool ----------
#define AVT 272   // v smem row stride bytes (128 fp16 + pad)
#define AVAH 0
#define AVVH 9216
__global__ void __launch_bounds__(256) k_attn_v_mma(const float* __restrict__ temp){
    __shared__ __align__(16) char sm[26624];
    uint32_t sb = smem_u32(sm);
    int tid = threadIdx.x, wid = tid >> 5, lid = tid & 31;
    int warp_m = wid >> 1, warp_n = wid & 1;
    int bh = blockIdx.y;
    int bb = bh >> 2, h = bh & 3;
    int n0 = blockIdx.x * 128;

    // stage attn: fused L2-norm scaling + softmax + fp16 round (row stride 144B)
    {
        int d = tid >> 2, e0 = (tid & 3)*16;
        const float* src = g_attn + (size_t)bh*HD*HD + d*64 + e0;
        float invq = 1.f / fmaxf(sqrtf(g_sqq[bh*64 + d]), 1e-12f);
        float tq = temp[bh & 3] * invq;
        float l[16];
        #pragma unroll
        for (int j = 0; j < 16; j++){
            float invk = 1.f / fmaxf(sqrtf(g_sqk[bh*64 + e0 + j]), 1e-12f);
            l[j] = src[j] * tq * invk;
        }
        float m = -1e30f;
        #pragma unroll
        for (int j = 0; j < 16; j++) m = fmaxf(m, l[j]);
        m = fmaxf(m, __shfl_xor_sync(0xFFFFFFFF, m, 1));
        m = fmaxf(m, __shfl_xor_sync(0xFFFFFFFF, m, 2));
        float s = 0.f;
        #pragma unroll
        for (int j = 0; j < 16; j++){ l[j] = expf(l[j] - m); s += l[j]; }
        s += __shfl_xor_sync(0xFFFFFFFF, s, 1);
        s += __shfl_xor_sync(0xFFFFFFFF, s, 2);
        float inv = 1.f / s;
        uint32_t so = d*AQT + e0*2;
        #pragma unroll
        for (int j = 0; j < 8; j++)
            *(uint32_t*)(sm + AVAH + so + j*4) =
                pack_h2(__float2half(l[j*2]*inv), __float2half(l[j*2+1]*inv));
    }
    // stage v (64 x 128 fp16, raw copy, row stride 272B)
    {
        int e = tid >> 2, q = tid & 3;
        const uint4* src = (const uint4*)(g_v + ((size_t)(bb*Cc + h*64 + e))*Nn + n0) + q*4;
        uint4* dst = (uint4*)(sm + AVVH + e*AVT + q*64);
        #pragma unroll
        for (int j = 0; j < 4; j++) dst[j] = src[j];
    }
    __syncthreads();

    uint32_t aAo = (uint32_t)((warp_m*16 + (lid & 7) + ((lid >> 3) & 1)*8)*AQT + ((lid >> 4) & 1)*16);
    uint32_t aBo = (uint32_t)(((lid & 7) + ((lid >> 3) & 1)*8)*AVT + warp_n*128 + ((lid >> 4) & 1)*16);

    float acc[8][4] = {};
    #pragma unroll
    for (int ks = 0; ks < 4; ks++){
        uint32_t kro = (uint32_t)(ks*16)*AVT;
        uint32_t bh_[16], arh[4];
        #pragma unroll
        for (int j = 0; j < 4; j++)
            ldmx4t(bh_ + j*4, sb + AVVH + aBo + kro + j*32);
        ldmx4(arh, sb + AVAH + aAo + ks*32);
        #pragma unroll
        for (int ni = 0; ni < 8; ni++) mma_f16(acc[ni], arh, bh_[ni*2], bh_[ni*2+1]);
    }

    // epilogue: write attened fp16 (B,C,N) + pool partial sums (fp32 acc)
    int gid = lid >> 2, q4 = lid & 3;
    int d0 = warp_m*16 + gid;
    size_t row0 = ((size_t)(bb*Cc + h*64 + d0)) * Nn;
    size_t row1 = ((size_t)(bb*Cc + h*64 + d0 + 8)) * Nn;
    float s0 = 0.f, s1 = 0.f;
    #pragma unroll
    for (int ni = 0; ni < 8; ni++){
        int n = n0 + warp_n*64 + ni*8 + q4*2;
        *(uint32_t*)&g_att[row0 + n] = pack_h2(__float2half(acc[ni][0]), __float2half(acc[ni][1]));
        *(uint32_t*)&g_att[row1 + n] = pack_h2(__float2half(acc[ni][2]), __float2half(acc[ni][3]));
        s0 += acc[ni][0] + acc[ni][1];
        s1 += acc[ni][2] + acc[ni][3];
    }
    s0 += __shfl_xor_sync(0xFFFFFFFF, s0, 1);
    s0 += __shfl_xor_sync(0xFFFFFFFF, s0, 2);
    s1 += __shfl_xor_sync(0xFFFFFFFF, s1, 1);
    s1 += __shfl_xor_sync(0xFFFFFFFF, s1, 2);
    if (q4 == 0){
        atomicAdd(&g_pool[bb*Cc + h*64 + d0], s0);
        atomicAdd(&g_pool[bb*Cc + h*64 + d0 + 8], s1);
    }
}

// ---------------- 6: fused depthwise conv + GELU + spatial interaction ---------
// Block = (b, 4 rows x 64 cols). Loops all 256 channels: conv+gelu -> g_conv,
// accumulate spatial MLP in registers -> g_gs.
__global__ void __launch_bounds__(256) k_conv_sp(const float* __restrict__ dww,
                                                 const float* __restrict__ dwb,
                                                 const float* __restrict__ w1,
                                                 const float* __restrict__ b1,
                                                 const float* __restrict__ w2,
                                                 const float* __restrict__ b2){
    __shared__ float swk[256*9];
    __shared__ float sbias[256];
    __shared__ float sw1[16*256];
    int bb = blockIdx.x >> 4;
    int y0 = (blockIdx.x & 15) * 4;
    int tid = threadIdx.x;
    for (int i = tid; i < 2304; i += 256) swk[i] = dww[i];
    sbias[tid] = dwb[tid];
    for (int i = tid; i < 4096; i += 256) sw1[i] = w1[i];
    __syncthreads();

    int y = y0 + (tid >> 6), x = tid & 63;
    int p = y*64 + x;
    bool xm = x > 0, xp = x < 63, ym = y > 0, yp = y < 63;
    float acc[16];
    #pragma unroll
    for (int o = 0; o < 16; o++) acc[o] = b1[o];

    const __half* vb = g_v + (size_t)bb * Cc * Nn;
    __half* cb = g_conv + (size_t)bb * Cc * Nn;
    #pragma unroll 2
    for (int c = 0; c < 256; c++){
        const __half* pl = vb + (size_t)c * Nn + p;
        const float* wk = swk + c*9;
        float s = sbias[c];
        if (ym){
            if (xm) s += __half2float(pl[-65]) * wk[0];
            s += __half2float(pl[-64]) * wk[1];
            if (xp) s += __half2float(pl[-63]) * wk[2];
        }
        if (xm) s += __half2float(pl[-1]) * wk[3];
        s += __half2float(pl[0]) * wk[4];
        if (xp) s += __half2float(pl[1]) * wk[5];
        if (yp){
            if (xm) s += __half2float(pl[63]) * wk[6];
            s += __half2float(pl[64]) * wk[7];
            if (xp) s += __half2float(pl[65]) * wk[8];
        }
        float val = gelu_f(s);
        cb[(size_t)c * Nn + p] = __float2half(val);
        #pragma unroll
        for (int o = 0; o < 16; o++) acc[o] += val * sw1[o*256 + c];
    }
    float sm2 = b2[0];
    #pragma unroll
    for (int o = 0; o < 16; o++) sm2 += gelu_f(acc[o]) * w2[o];
    g_gs[bb*Nn + p] = sigmoid_f(sm2);
}

// ---------------- 7: channel interaction SE -> gc = sigmoid(map) ---------------
__global__ void k_channel_mlp(const float* __restrict__ w1, const float* __restrict__ b1,
                              const float* __restrict__ w2, const float* __restrict__ b2){
    int bb = blockIdx.x;
    int tid = threadIdx.x;
    __shared__ float sp[256];
    __shared__ float h1[32];
    sp[tid] = g_pool[bb*Cc + tid] * (1.f / Nn);
    __syncthreads();
    if (tid < 32){
        float a = b1[tid];
        for (int c = 0; c < 256; c++) a += sp[c] * w1[tid*256 + c];
        h1[tid] = gelu_f(a);
    }
    __syncthreads();
    float a = b2[tid];
    #pragma unroll
    for (int j = 0; j < 32; j++) a += h1[j] * w2[tid*32 + j];
    g_gc[bb*Cc + tid] = sigmoid_f(a);
}

// ---------------- 8: proj GEMM via mma.sync fp16, fused gating, reg prefetch ---
#define PAH 0
#define PBH 10240
#define PBT 272
__global__ void __launch_bounds__(256) k_proj_mma(const float* __restrict__ bias,
                                                  float* __restrict__ out){
    __shared__ __align__(16) char sm[18944];
    uint32_t sb = smem_u32(sm);
    int tid = threadIdx.x, wid = tid >> 5, lid = tid & 31;
    int warp_m = wid >> 2, warp_n = wid & 3;
    int cblk = blockIdx.x * 128;         // o block
    int bn0  = blockIdx.y * 128;
    int bb = bn0 >> 12, n0 = bn0 & (Nn-1);

    int gr = tid >> 1, ghf = tid & 1;
    const char* pah = (const char*)(g_wP_h + (size_t)(cblk + gr)*256) + ghf*32;
    char* dA = sm + gr*80 + ghf*32;

    int cr = tid >> 3, ncb = (tid & 7) * 16;
    const __half* At = g_att  + (size_t)(bb*Cc) * Nn + n0 + ncb;
    const __half* Cv = g_conv + (size_t)(bb*Cc) * Nn + n0 + ncb;
    float gsa[16];
    #pragma unroll
    for (int j = 0; j < 4; j++){
        float4 g4 = *(const float4*)&g_gs[bb*Nn + n0 + ncb + j*4];
        gsa[j*4] = g4.x; gsa[j*4+1] = g4.y; gsa[j*4+2] = g4.z; gsa[j*4+3] = g4.w;
    }
    char* dB = sm + PBH + cr*PBT + ncb*2;

    uint32_t aAo = (uint32_t)((warp_m*64 + (lid & 7) + ((lid >> 3) & 1)*8)*80 + ((lid >> 4) & 1)*16);
    uint32_t aBo = (uint32_t)(((lid & 7) + ((lid >> 3) & 1)*8)*PBT + warp_n*64 + ((lid >> 4) & 1)*16);

    float acc[4][4][4] = {};

    uint4 rA0, rA1;
    uint2 rAt[4], rCv[4];
    float rGc;
    #define PROJ_LOAD(kc_) do{ \
        int c0_ = (kc_) * 32; \
        rA0 = *(const uint4*)(pah + c0_*2); \
        rA1 = *(const uint4*)(pah + c0_*2 + 16); \
        rGc = g_gc[bb*Cc + c0_ + cr]; \
        const uint2* at_ = (const uint2*)(At + (size_t)(c0_ + cr) * Nn); \
        const uint2* cv_ = (const uint2*)(Cv + (size_t)(c0_ + cr) * Nn); \
        rAt[0] = at_[0]; rAt[1] = at_[1]; rAt[2] = at_[2]; rAt[3] = at_[3]; \
        rCv[0] = cv_[0]; rCv[1] = cv_[1]; rCv[2] = cv_[2]; rCv[3] = cv_[3]; \
    } while(0)

    PROJ_LOAD(0);

    #pragma unroll 1
    for (int kc = 0; kc < 8; kc++){
        *(uint4*)(dA + PAH)      = rA0;
        *(uint4*)(dA + PAH + 16) = rA1;
        {
            uint32_t o[8];
            #pragma unroll
            for (int jj = 0; jj < 4; jj++){
                __half2 a0 = *(__half2*)&rAt[jj].x, a1 = *(__half2*)&rAt[jj].y;
                __half2 c0h = *(__half2*)&rCv[jj].x, c1h = *(__half2*)&rCv[jj].y;
                float2 a = __half22float2(a0), c = __half22float2(c0h);
                float2 a2 = __half22float2(a1), c2 = __half22float2(c1h);
                float v0 = a.x*gsa[jj*4]   + c.x*rGc;
                float v1 = a.y*gsa[jj*4+1] + c.y*rGc;
                float v2 = a2.x*gsa[jj*4+2] + c2.x*rGc;
                float v3 = a2.y*gsa[jj*4+3] + c2.y*rGc;
                o[jj*2]   = pack_h2(__float2half(v0), __float2half(v1));
                o[jj*2+1] = pack_h2(__float2half(v2), __float2half(v3));
            }
            *(uint4*)(dB)      = make_uint4(o[0], o[1], o[2], o[3]);
            *(uint4*)(dB + 16) = make_uint4(o[4], o[5], o[6], o[7]);
        }
        __syncthreads();
        if (kc < 7) PROJ_LOAD(kc + 1);
        #pragma unroll
        for (int ks = 0; ks < 2; ks++){
            uint32_t kro = (uint32_t)(ks*16)*PBT;
            uint32_t bh[8], arh[4];
            ldmx4t(bh,     sb + PBH + aBo + kro);
            ldmx4t(bh + 4, sb + PBH + aBo + kro + 32);
            uint32_t kofs = ks*32;
            #pragma unroll
            for (int mi = 0; mi < 4; mi++){
                ldmx4(arh, sb + PAH + aAo + kofs + (uint32_t)(mi*16)*80);
                #pragma unroll
                for (int ni = 0; ni < 4; ni++) mma_f16(acc[mi][ni], arh, bh[ni*2], bh[ni*2+1]);
            }
        }
        __syncthreads();
    }

    int gid = lid >> 2, q4 = lid & 3;
    int obase = cblk + warp_m*64 + gid;
    #pragma unroll
    for (int mi = 0; mi < 4; mi++){
        int o0 = obase + mi*16;
        float bo0 = bias[o0], bo1 = bias[o0 + 8];
        float* r0 = out + ((size_t)(bb*Cc + o0)) * Nn;
        float* r1 = out + ((size_t)(bb*Cc + o0 + 8)) * Nn;
        #pragma unroll
        for (int ni = 0; ni < 4; ni++){
            int n = n0 + warp_n*32 + ni*8 + q4*2;
            *(float2*)&r0[n] = make_float2(acc[mi][ni][0] + bo0, acc[mi][ni][1] + bo0);
            *(float2*)&r1[n] = make_float2(acc[mi][ni][2] + bo1, acc[mi][ni][3] + bo1);
        }
    }
}

// =================================================================================
extern "C" void kernel_launch(void* const* d_in, const int* in_sizes, int n_in,
                              void* d_out, int out_size){
    const float* x     = (const float*)d_in[0];
    const float* ln_g  = (const float*)d_in[1];
    const float* ln_b  = (const float*)d_in[2];
    const float* w_qkv = (const float*)d_in[3];
    const float* w_q   = (const float*)d_in[4];
    const float* b_q   = (const float*)d_in[5];
    const float* temp  = (const float*)d_in[6];
    const float* dw_w  = (const float*)d_in[7];
    const float* dw_b  = (const float*)d_in[8];
    const float* ci_w1 = (const float*)d_in[9];
    const float* ci_b1 = (const float*)d_in[10];
    const float* ci_w2 = (const float*)d_in[11];
    const float* ci_b2 = (const float*)d_in[12];
    const float* si_w1 = (const float*)d_in[13];
    const float* si_b1 = (const float*)d_in[14];
    const float* si_w2 = (const float*)d_in[15];
    const float* si_b2 = (const float*)d_in[16];
    const float* pj_w  = (const float*)d_in[17];
    const float* pj_b  = (const float*)d_in[18];
    float* out = (float*)d_out;

    cudaFuncSetAttribute(k_qkv_mma, cudaFuncAttributeMaxDynamicSharedMemorySize, QKV_SMEM);

    k_zero<<<512, 256>>>();
    k_layernorm<<<Bq*(Nn/32), 256>>>(x, ln_g, ln_b);
    k_buildWP<<<320, 256>>>(w_qkv, w_q, pj_w);
    k_qkv_mma<<<dim3(6, BN/128), 256, QKV_SMEM>>>(b_q);     // 4th launch -> profiled
    k_attn_qk_mma<<<dim3(8, Bq*NH), 256>>>();
    k_attn_v_mma<<<dim3(Nn/128, Bq*NH), 256>>>(temp);
    k_conv_sp<<<Bq*16, 256>>>(dw_w, dw_b, si_w1, si_b1, si_w2, si_b2);
    k_channel_mlp<<<Bq, 256>>>(ci_w1, ci_b1, ci_w2, ci_b2);
    k_proj_mma<<<dim3(2, BN/128), 256>>>(pj_b, out);
}

// round 12
// speedup vs baseline: 1.3466x; 1.3466x over previous
#include <cuda_runtime.h>
#include <cuda_fp16.h>
#include <math.h>
#include <stdint.h>

// Problem constants
#define Bq   8
#define Cc   256
#define Hh   64
#define Ww   64
#define Nn   4096            // H*W
#define NH   4
#define HD   64
#define BN   (Bq*Nn)         // 32768

// ---------------- scratch (device globals; no allocation allowed) -------------
__device__ __half g_xn_h[BN*Cc];     // layernormed x (fp16 rounded), [b*N+n][c]
__device__ __half g_wB_h[768*Cc];    // folded qkv weight [o][c], fp16 hi
__device__ __half g_wB_l[768*Cc];    // fp16 lo residual
__device__ __half g_wP_h[Cc*Cc];     // proj weight transposed [o][c], fp16 (rounded)
__device__ __half g_qh[Bq*Cc*Nn];    // q fp16 (rounded), row = bh*64+d, col n
__device__ __half g_kh[Bq*Cc*Nn];    // k fp16 hi
__device__ __half g_kl[Bq*Cc*Nn];    // k fp16 lo
__device__ __half g_v   [Bq*Cc*Nn];  // v fp16, (B,C,N) head-major
__device__ __half g_att [Bq*Cc*Nn];  // attened_x fp16, (B,C,N)
__device__ __half g_conv[Bq*Cc*Nn];  // gelu(dwconv) fp16, (B,C,N)
__device__ float g_attn[Bq*NH*HD*HD];  // raw logits q@k^T, (B,nh,hd,hd)
__device__ float g_pool[Bq*Cc];        // sum over n of attened
__device__ float g_gc  [Bq*Cc];        // sigmoid(channel_map)
__device__ float g_gs  [Bq*Nn];        // sigmoid(spatial_map)
__device__ float g_sqq [Bq*Cc];        // sum of squares per q row
__device__ float g_sqk [Bq*Cc];

__device__ __forceinline__ float gelu_f(float x){
    return 0.5f * x * (1.0f + erff(x * 0.70710678118654752f));
}
__device__ __forceinline__ float sigmoid_f(float x){
    return 1.0f / (1.0f + expf(-x));
}
__device__ __forceinline__ uint32_t smem_u32(const void* p){
    uint32_t a;
    asm("{ .reg .u64 t; cvta.to.shared.u64 t, %1; cvt.u32.u64 %0, t; }" : "=r"(a) : "l"(p));
    return a;
}
__device__ __forceinline__ void ldmx4(uint32_t* r, uint32_t addr){
    asm volatile("ldmatrix.sync.aligned.m8n8.x4.shared.b16 {%0,%1,%2,%3}, [%4];"
                 : "=r"(r[0]), "=r"(r[1]), "=r"(r[2]), "=r"(r[3]) : "r"(addr));
}
__device__ __forceinline__ void ldmx4t(uint32_t* r, uint32_t addr){
    asm volatile("ldmatrix.sync.aligned.m8n8.x4.trans.shared.b16 {%0,%1,%2,%3}, [%4];"
                 : "=r"(r[0]), "=r"(r[1]), "=r"(r[2]), "=r"(r[3]) : "r"(addr));
}
__device__ __forceinline__ void mma_f16(float* d, const uint32_t* a, uint32_t b0, uint32_t b1){
    asm volatile(
        "mma.sync.aligned.m16n8k16.row.col.f32.f16.f16.f32 "
        "{%0,%1,%2,%3}, {%4,%5,%6,%7}, {%8,%9}, {%0,%1,%2,%3};"
        : "+f"(d[0]), "+f"(d[1]), "+f"(d[2]), "+f"(d[3])
        : "r"(a[0]), "r"(a[1]), "r"(a[2]), "r"(a[3]), "r"(b0), "r"(b1));
}
__device__ __forceinline__ void cpa16(uint32_t d, const void* s){
    asm volatile("cp.async.cg.shared.global [%0], [%1], 16;" :: "r"(d), "l"(s));
}
__device__ __forceinline__ uint32_t pack_h2(__half a, __half b){
    return ((uint32_t)__half_as_ushort(b) << 16) | (uint32_t)__half_as_ushort(a);
}
__device__ __forceinline__ void split_h(float v, __half& h, __half& l){
    h = __float2half(v);
    l = __float2half(v - __half2float(h));
}

// qkv pipeline smem: k-chunk 32 fp16 = 64B rows padded to 80B; 3 arrays/stage, 3 stages
#define QT    80
#define QSTG  30720
#define QAH   0
#define QAL   10240
#define QBH   20480
#define QKV_SMEM 92160

// ---------------- 0: zero the accumulated buffers -----------------------------
__global__ void k_zero(){
    int i = blockIdx.x * 256 + threadIdx.x;
    if (i < Bq*NH*HD*HD) g_attn[i] = 0.f;
    if (i < Bq*Cc){ g_pool[i] = 0.f; g_sqq[i] = 0.f; g_sqk[i] = 0.f; }
}

// ---------------- 1: LayerNorm over C -> g_xn_h fp16, layout [b*N+n][c] --------
__global__ void k_layernorm(const float* __restrict__ x,
                            const float* __restrict__ g,
                            const float* __restrict__ b){
    __shared__ float sx[256][33];
    __shared__ float spart[8][32];
    __shared__ float smu[32], sinv[32];
    int bb = blockIdx.x >> 7;
    int n0 = (blockIdx.x & 127) * 32;
    int tid = threadIdx.x;
    int nl = tid & 31, part = tid >> 5;
    const float* xb = x + (size_t)bb * Cc * Nn + n0;
    #pragma unroll
    for (int c0 = 0; c0 < 256; c0 += 8)
        sx[c0 + part][nl] = xb[(size_t)(c0 + part) * Nn + nl];
    __syncthreads();
    float s = 0.f, s2 = 0.f;
    #pragma unroll
    for (int i = 0; i < 32; i++){ float v = sx[part*32 + i][nl]; s += v; s2 += v*v; }
    spart[part][nl] = s;
    __syncthreads();
    if (part == 0){ float t = 0.f; for (int p = 0; p < 8; p++) t += spart[p][nl]; smu[nl] = t * (1.f/256.f); }
    __syncthreads();
    spart[part][nl] = s2;
    __syncthreads();
    if (part == 0){
        float t = 0.f; for (int p = 0; p < 8; p++) t += spart[p][nl];
        float mu = smu[nl];
        sinv[nl] = rsqrtf(t * (1.f/256.f) - mu*mu + 1e-5f);
    }
    __syncthreads();
    float gc = g[tid], bc = b[tid];
    for (int n = 0; n < 32; n++){
        float val = (sx[tid][n] - smu[n]) * sinv[n] * gc + bc;
        g_xn_h[((size_t)(bb * Nn) + n0 + n) * 256 + tid] = __float2half(val);
    }
}

// ---------------- 2: merged weight prep: buildW (blocks 0..255) + buildP -------
__global__ void k_buildWP(const float* __restrict__ wqkv, const float* __restrict__ wq,
                          const float* __restrict__ wp){
    int blk = blockIdx.x;
    int tid = threadIdx.x;
    if (blk < 256){
        __shared__ float srow[768];
        __shared__ float swq[64*64];
        int c = blk;
        for (int i = tid; i < 768; i += 256)  srow[i] = wqkv[(size_t)c*768 + i];
        for (int i = tid; i < 4096; i += 256) swq[i]  = wq[i];
        __syncthreads();
        int h = tid >> 6, d = tid & 63;
        float s = 0.f;
        #pragma unroll 16
        for (int e = 0; e < 64; e++) s += srow[h*64 + e] * swq[e*64 + d];
        float vals[3] = { s, srow[256 + tid], srow[512 + tid] };
        #pragma unroll
        for (int t = 0; t < 3; t++){
            int o = t*256 + tid;
            __half hi, lo; split_h(vals[t], hi, lo);
            g_wB_h[(size_t)o*256 + c] = hi;
            g_wB_l[(size_t)o*256 + c] = lo;
        }
    } else {
        __shared__ float t[32][33];
        int bp = blk - 256;
        int tx = tid & 31, ty = tid >> 5;   // 32 x 8
        int c0 = (bp & 7) * 32, o0 = (bp >> 3) * 32;
        #pragma unroll
        for (int r = 0; r < 32; r += 8)
            t[ty + r][tx] = wp[(size_t)(c0 + ty + r) * 256 + o0 + tx];
        __syncthreads();
        #pragma unroll
        for (int r = 0; r < 32; r += 8)
            g_wP_h[(size_t)(o0 + ty + r) * 256 + c0 + tx] = __float2half(t[tx][ty + r]);
    }
}

// ---------------- 3: qkv GEMM via mma.sync fp16x2, 3-stage, 1 sync/chunk -------
#define QKV_ISSUE(kc_) do{ \
    uint32_t d_ = drow + ((kc_) % 3) * QSTG; \
    size_t go_ = (size_t)(kc_) * 64; \
    cpa16(d_ + QAH,      pwh + go_);      cpa16(d_ + QAH + 16, pwh + go_ + 16); \
    cpa16(d_ + QAL,      pwl + go_);      cpa16(d_ + QAL + 16, pwl + go_ + 16); \
    cpa16(d_ + QBH,      pxh + go_);      cpa16(d_ + QBH + 16, pxh + go_ + 16); \
    asm volatile("cp.async.commit_group;"); } while(0)

__global__ void __launch_bounds__(256, 2) k_qkv_mma(const float* __restrict__ bq){
    extern __shared__ char dsm[];
    uint32_t sb = smem_u32(dsm);
    int tid = threadIdx.x, wid = tid >> 5, lid = tid & 31;
    int warp_m = wid >> 2, warp_n = wid & 3;
    int cblk = blockIdx.x * 128;
    int bn0  = blockIdx.y * 128;
    int bb = bn0 >> 12, n0 = bn0 & (Nn-1);

    int gr = tid >> 1, ghf = tid & 1;
    const char* pwh = (const char*)(g_wB_h + (size_t)(cblk + gr)*256) + ghf*32;
    const char* pwl = (const char*)(g_wB_l + (size_t)(cblk + gr)*256) + ghf*32;
    const char* pxh = (const char*)(g_xn_h + (size_t)(bn0  + gr)*256) + ghf*32;
    uint32_t drow = sb + gr*QT + ghf*32;

    QKV_ISSUE(0);
    QKV_ISSUE(1);

    uint32_t aAo = (uint32_t)((warp_m*64 + (lid & 7) + ((lid >> 3) & 1)*8)*QT + ((lid >> 4) & 1)*16);
    uint32_t aBo = (uint32_t)((warp_n*32 + (lid & 7) + ((lid >> 4) & 1)*8)*QT + ((lid >> 3) & 1)*16);

    float acc[4][4][4] = {};

    #pragma unroll 1
    for (int kc = 0; kc < 8; kc++){
        if (kc < 7) asm volatile("cp.async.wait_group 1;");
        else        asm volatile("cp.async.wait_group 0;");
        __syncthreads();
        if (kc < 6) QKV_ISSUE(kc + 2);
        uint32_t base = sb + (kc % 3)*QSTG;
        #pragma unroll
        for (int ks = 0; ks < 2; ks++){
            uint32_t kofs = ks*32;
            uint32_t bh[8], arh[4], arl[4];
            ldmx4(bh,     base + QBH + aBo + kofs);
            ldmx4(bh + 4, base + QBH + aBo + kofs + 16*QT);
            #pragma unroll
            for (int mi = 0; mi < 4; mi++){
                ldmx4(arh, base + QAH + aAo + kofs + (uint32_t)(mi*16)*QT);
                ldmx4(arl, base + QAL + aAo + kofs + (uint32_t)(mi*16)*QT);
                #pragma unroll
                for (int ni = 0; ni < 4; ni++) mma_f16(acc[mi][ni], arh, bh[ni*2], bh[ni*2+1]);
                #pragma unroll
                for (int ni = 0; ni < 4; ni++) mma_f16(acc[mi][ni], arl, bh[ni*2], bh[ni*2+1]);
            }
        }
    }

    // epilogue: q -> fp16 (+norms), k -> fp16 hi/lo (+norms), v -> fp16
    int gid = lid >> 2, q4 = lid & 3;
    int obase = cblk + warp_m*64 + gid;
    int ot = obase >> 8;                 // 0=q,1=k,2=v (constant per block)
    #pragma unroll
    for (int mi = 0; mi < 4; mi++){
        int o0 = obase + mi*16;
        float bo0 = (ot == 0) ? bq[o0 & 63] : 0.f;
        float bo1 = (ot == 0) ? bq[(o0 + 8) & 63] : 0.f;
        size_t row0 = ((size_t)(bb*Cc + (o0 & 255))) * Nn;
        size_t row1 = ((size_t)(bb*Cc + ((o0 + 8) & 255))) * Nn;
        float s0 = 0.f, s1 = 0.f;
        #pragma unroll
        for (int ni = 0; ni < 4; ni++){
            int n = n0 + warp_n*32 + ni*8 + q4*2;
            float v0 = acc[mi][ni][0] + bo0, v1 = acc[mi][ni][1] + bo0;
            float v2 = acc[mi][ni][2] + bo1, v3 = acc[mi][ni][3] + bo1;
            if (ot == 2){
                *(uint32_t*)&g_v[row0 + n] = pack_h2(__float2half(v0), __float2half(v1));
                *(uint32_t*)&g_v[row1 + n] = pack_h2(__float2half(v2), __float2half(v3));
            } else if (ot == 0){
                *(uint32_t*)&g_qh[row0 + n] = pack_h2(__float2half(v0), __float2half(v1));
                *(uint32_t*)&g_qh[row1 + n] = pack_h2(__float2half(v2), __float2half(v3));
                s0 += v0*v0 + v1*v1;
                s1 += v2*v2 + v3*v3;
            } else {
                __half h0,l0,h1,l1,h2,l2,h3,l3;
                split_h(v0,h0,l0); split_h(v1,h1,l1);
                split_h(v2,h2,l2); split_h(v3,h3,l3);
                *(uint32_t*)&g_kh[row0 + n] = pack_h2(h0, h1);
                *(uint32_t*)&g_kl[row0 + n] = pack_h2(l0, l1);
                *(uint32_t*)&g_kh[row1 + n] = pack_h2(h2, h3);
                *(uint32_t*)&g_kl[row1 + n] = pack_h2(l2, l3);
                s0 += v0*v0 + v1*v1;
                s1 += v2*v2 + v3*v3;
            }
        }
        if (ot < 2){
            s0 += __shfl_xor_sync(0xFFFFFFFF, s0, 1);
            s0 += __shfl_xor_sync(0xFFFFFFFF, s0, 2);
            s1 += __shfl_xor_sync(0xFFFFFFFF, s1, 1);
            s1 += __shfl_xor_sync(0xFFFFFFFF, s1, 2);
            if (q4 == 0){
                float* sq = ot ? g_sqk : g_sqq;
                atomicAdd(&sq[bb*Cc + (o0 & 255)], s0);
                atomicAdd(&sq[bb*Cc + ((o0 + 8) & 255)], s1);
            }
        }
    }
}

// ---------------- 4: attn logits = q @ k^T, cp.async 2-stage --------------------
#define AQT   144   // 72 fp16 row stride (bytes)
#define AQSTG 27648 // 3 arrays x 64 x 144
__global__ void __launch_bounds__(256) k_attn_qk_mma(){
    __shared__ __align__(16) char sm[2*AQSTG];
    uint32_t sb = smem_u32(sm);
    const int OQH = 0, OKH = 64*AQT, OKL = 2*64*AQT;
    int tid = threadIdx.x, wid = tid >> 5, lid = tid & 31;
    int warp_m = wid >> 1, warp_n = wid & 1;
    int bh = blockIdx.y;
    int nbase = blockIdx.x * 512;

    int r_ = tid >> 2, c16_ = (tid & 3)*2;   // 2 chunks of 16B per thread
    size_t gbase = ((size_t)(bh*64 + r_))*Nn;
    uint32_t sobase = r_*AQT + c16_*16;

    #define AQ_ISSUE(kc_) do{ \
        uint32_t st_ = sb + ((kc_) & 1)*AQSTG + sobase; \
        size_t g_ = gbase + (size_t)(nbase + (kc_)*64) + c16_*8; \
        cpa16(st_ + OQH,      g_qh + g_);  cpa16(st_ + OQH + 16, g_qh + g_ + 8); \
        cpa16(st_ + OKH,      g_kh + g_);  cpa16(st_ + OKH + 16, g_kh + g_ + 8); \
        cpa16(st_ + OKL,      g_kl + g_);  cpa16(st_ + OKL + 16, g_kl + g_ + 8); \
        asm volatile("cp.async.commit_group;"); } while(0)

    AQ_ISSUE(0);

    uint32_t aAo = (uint32_t)((warp_m*16 + (lid & 7) + ((lid >> 3) & 1)*8)*AQT + ((lid >> 4) & 1)*16);
    uint32_t aBo = (uint32_t)((warp_n*32 + (lid & 7) + ((lid >> 4) & 1)*8)*AQT + ((lid >> 3) & 1)*16);

    float acc[4][4] = {};

    #pragma unroll 1
    for (int kc = 0; kc < 8; kc++){
        asm volatile("cp.async.wait_group 0;");
        __syncthreads();
        if (kc < 7) AQ_ISSUE(kc + 1);
        uint32_t base = sb + (kc & 1)*AQSTG;
        #pragma unroll
        for (int ks = 0; ks < 4; ks++){
            uint32_t kofs = ks*32;
            uint32_t bh_[8], bl_[8], arh[4];
            ldmx4(bh_,     base + OKH + aBo + kofs);
            ldmx4(bh_ + 4, base + OKH + aBo + kofs + 16*AQT);
            ldmx4(bl_,     base + OKL + aBo + kofs);
            ldmx4(bl_ + 4, base + OKL + aBo + kofs + 16*AQT);
            ldmx4(arh, base + OQH + aAo + kofs);
            #pragma unroll
            for (int ni = 0; ni < 4; ni++) mma_f16(acc[ni], arh, bh_[ni*2], bh_[ni*2+1]);
            #pragma unroll
            for (int ni = 0; ni < 4; ni++) mma_f16(acc[ni], arh, bl_[ni*2], bl_[ni*2+1]);
        }
        __syncthreads();
    }

    int gid = lid >> 2, q4 = lid & 3;
    float* dst = g_attn + (size_t)bh*HD*HD;
    #pragma unroll
    for (int ni = 0; ni < 4; ni++){
        int e = warp_n*32 + ni*8 + q4*2;
        int d0 = warp_m*16 + gid;
        atomicAdd(&dst[d0*64 + e],     acc[ni][0]);
        atomicAdd(&dst[d0*64 + e + 1], acc[ni][1]);
        atomicAdd(&dst[(d0+8)*64 + e],     acc[ni][2]);
        atomicAdd(&dst[(d0+8)*64 + e + 1], acc[ni][3]);
    }
}

// ---------------- 5: attened = softmax(attn) @ v, fused softmax + pool ----------
#define AVT 272   // v smem row stride bytes (128 fp16 + pad)
#define AVAH 0
#define AVVH 9216
__global__ void __launch_bounds__(256) k_attn_v_mma(const float* __restrict__ temp){
    __shared__ __align__(16) char sm[26624];
    uint32_t sb = smem_u32(sm);
    int tid = threadIdx.x, wid = tid >> 5, lid = tid & 31;
    int warp_m = wid >> 1, warp_n = wid & 1;
    int bh = blockIdx.y;
    int bb = bh >> 2, h = bh & 3;
    int n0 = blockIdx.x * 128;

    // stage attn: fused L2-norm scaling + softmax + fp16 round (row stride 144B)
    {
        int d = tid >> 2, e0 = (tid & 3)*16;
        const float* src = g_attn + (size_t)bh*HD*HD + d*64 + e0;
        float invq = 1.f / fmaxf(sqrtf(g_sqq[bh*64 + d]), 1e-12f);
        float tq = temp[bh & 3] * invq;
        float l[16];
        #pragma unroll
        for (int j = 0; j < 16; j++){
            float invk = 1.f / fmaxf(sqrtf(g_sqk[bh*64 + e0 + j]), 1e-12f);
            l[j] = src[j] * tq * invk;
        }
        float m = -1e30f;
        #pragma unroll
        for (int j = 0; j < 16; j++) m = fmaxf(m, l[j]);
        m = fmaxf(m, __shfl_xor_sync(0xFFFFFFFF, m, 1));
        m = fmaxf(m, __shfl_xor_sync(0xFFFFFFFF, m, 2));
        float s = 0.f;
        #pragma unroll
        for (int j = 0; j < 16; j++){ l[j] = expf(l[j] - m); s += l[j]; }
        s += __shfl_xor_sync(0xFFFFFFFF, s, 1);
        s += __shfl_xor_sync(0xFFFFFFFF, s, 2);
        float inv = 1.f / s;
        uint32_t so = d*AQT + e0*2;
        #pragma unroll
        for (int j = 0; j < 8; j++)
            *(uint32_t*)(sm + AVAH + so + j*4) =
                pack_h2(__float2half(l[j*2]*inv), __float2half(l[j*2+1]*inv));
    }
    // stage v (64 x 128 fp16, raw copy, row stride 272B)
    {
        int e = tid >> 2, q = tid & 3;
        const uint4* src = (const uint4*)(g_v + ((size_t)(bb*Cc + h*64 + e))*Nn + n0) + q*4;
        uint4* dst = (uint4*)(sm + AVVH + e*AVT + q*64);
        #pragma unroll
        for (int j = 0; j < 4; j++) dst[j] = src[j];
    }
    __syncthreads();

    uint32_t aAo = (uint32_t)((warp_m*16 + (lid & 7) + ((lid >> 3) & 1)*8)*AQT + ((lid >> 4) & 1)*16);
    uint32_t aBo = (uint32_t)(((lid & 7) + ((lid >> 3) & 1)*8)*AVT + warp_n*128 + ((lid >> 4) & 1)*16);

    float acc[8][4] = {};
    #pragma unroll
    for (int ks = 0; ks < 4; ks++){
        uint32_t kro = (uint32_t)(ks*16)*AVT;
        uint32_t bh_[16], arh[4];
        #pragma unroll
        for (int j = 0; j < 4; j++)
            ldmx4t(bh_ + j*4, sb + AVVH + aBo + kro + j*32);
        ldmx4(arh, sb + AVAH + aAo + ks*32);
        #pragma unroll
        for (int ni = 0; ni < 8; ni++) mma_f16(acc[ni], arh, bh_[ni*2], bh_[ni*2+1]);
    }

    // epilogue: write attened fp16 (B,C,N) + pool partial sums (fp32 acc)
    int gid = lid >> 2, q4 = lid & 3;
    int d0 = warp_m*16 + gid;
    size_t row0 = ((size_t)(bb*Cc + h*64 + d0)) * Nn;
    size_t row1 = ((size_t)(bb*Cc + h*64 + d0 + 8)) * Nn;
    float s0 = 0.f, s1 = 0.f;
    #pragma unroll
    for (int ni = 0; ni < 8; ni++){
        int n = n0 + warp_n*64 + ni*8 + q4*2;
        *(uint32_t*)&g_att[row0 + n] = pack_h2(__float2half(acc[ni][0]), __float2half(acc[ni][1]));
        *(uint32_t*)&g_att[row1 + n] = pack_h2(__float2half(acc[ni][2]), __float2half(acc[ni][3]));
        s0 += acc[ni][0] + acc[ni][1];
        s1 += acc[ni][2] + acc[ni][3];
    }
    s0 += __shfl_xor_sync(0xFFFFFFFF, s0, 1);
    s0 += __shfl_xor_sync(0xFFFFFFFF, s0, 2);
    s1 += __shfl_xor_sync(0xFFFFFFFF, s1, 1);
    s1 += __shfl_xor_sync(0xFFFFFFFF, s1, 2);
    if (q4 == 0){
        atomicAdd(&g_pool[bb*Cc + h*64 + d0], s0);
        atomicAdd(&g_pool[bb*Cc + h*64 + d0 + 8], s1);
    }
}

// ---------------- 6: depthwise 3x3 conv + GELU on v fp16 (one plane per block) -
__global__ void k_dwconv(const float* __restrict__ w, const float* __restrict__ bias){
    int bc = blockIdx.x;
    int c  = bc & (Cc-1);
    const __half* plane = g_v + (size_t)bc * Nn;
    float wk[9];
    #pragma unroll
    for (int i = 0; i < 9; i++) wk[i] = w[c*9 + i];
    float bb = bias[c];
    for (int p = threadIdx.x; p < Nn; p += 256){
        int y = p >> 6, x = p & 63;
        float s = bb;
        #pragma unroll
        for (int dy = -1; dy <= 1; dy++){
            int yy = y + dy;
            if (yy < 0 || yy >= Hh) continue;
            #pragma unroll
            for (int dx = -1; dx <= 1; dx++){
                int xx = x + dx;
                if (xx < 0 || xx >= Ww) continue;
                s += __half2float(plane[yy*Ww + xx]) * wk[(dy+1)*3 + dx + 1];
            }
        }
        g_conv[(size_t)bc * Nn + p] = __float2half(gelu_f(s));
    }
}

// ---------------- 7: spatial interaction -> gs = sigmoid(map) ------------------
__global__ void k_spatial(const float* __restrict__ w1, const float* __restrict__ b1,
                          const float* __restrict__ w2, const float* __restrict__ b2){
    int bb = blockIdx.x >> 4;
    int n  = (blockIdx.x & 15) * 256 + threadIdx.x;
    __shared__ float sw1[16*256];
    for (int i = threadIdx.x; i < 16*256; i += 256) sw1[i] = w1[i];
    __syncthreads();
    float acc[16];
    #pragma unroll
    for (int o = 0; o < 16; o++) acc[o] = b1[o];
    const __half* cb = g_conv + (size_t)bb * Cc * Nn + n;
    for (int c = 0; c < 256; c++){
        float x = __half2float(cb[(size_t)c * Nn]);
        #pragma unroll
        for (int o = 0; o < 16; o++) acc[o] += x * sw1[o*256 + c];
    }
    float sm = b2[0];
    #pragma unroll
    for (int o = 0; o < 16; o++) sm += gelu_f(acc[o]) * w2[o];
    g_gs[bb*Nn + n] = sigmoid_f(sm);
}

// ---------------- 8: channel interaction SE -> gc = sigmoid(map) ---------------
__global__ void k_channel_mlp(const float* __restrict__ w1, const float* __restrict__ b1,
                              const float* __restrict__ w2, const float* __restrict__ b2){
    int bb = blockIdx.x;
    int tid = threadIdx.x;
    __shared__ float sp[256];
    __shared__ float h1[32];
    sp[tid] = g_pool[bb*Cc + tid] * (1.f / Nn);
    __syncthreads();
    if (tid < 32){
        float a = b1[tid];
        for (int c = 0; c < 256; c++) a += sp[c] * w1[tid*256 + c];
        h1[tid] = gelu_f(a);
    }
    __syncthreads();
    float a = b2[tid];
    #pragma unroll
    for (int j = 0; j < 32; j++) a += h1[j] * w2[tid*32 + j];
    g_gc[bb*Cc + tid] = sigmoid_f(a);
}

// ---------------- 9: proj GEMM via mma.sync fp16, fused gating, reg prefetch ---
#define PAH 0
#define PBH 10240
#define PBT 272
__global__ void __launch_bounds__(256) k_proj_mma(const float* __restrict__ bias,
                                                  float* __restrict__ out){
    __shared__ __align__(16) char sm[18944];
    uint32_t sb = smem_u32(sm);
    int tid = threadIdx.x, wid = tid >> 5, lid = tid & 31;
    int warp_m = wid >> 2, warp_n = wid & 3;
    int cblk = blockIdx.x * 128;         // o block
    int bn0  = blockIdx.y * 128;
    int bb = bn0 >> 12, n0 = bn0 & (Nn-1);

    int gr = tid >> 1, ghf = tid & 1;
    const char* pah = (const char*)(g_wP_h + (size_t)(cblk + gr)*256) + ghf*32;
    char* dA = sm + gr*80 + ghf*32;

    int cr = tid >> 3, ncb = (tid & 7) * 16;
    const __half* At = g_att  + (size_t)(bb*Cc) * Nn + n0 + ncb;
    const __half* Cv = g_conv + (size_t)(bb*Cc) * Nn + n0 + ncb;
    float gsa[16];
    #pragma unroll
    for (int j = 0; j < 4; j++){
        float4 g4 = *(const float4*)&g_gs[bb*Nn + n0 + ncb + j*4];
        gsa[j*4] = g4.x; gsa[j*4+1] = g4.y; gsa[j*4+2] = g4.z; gsa[j*4+3] = g4.w;
    }
    char* dB = sm + PBH + cr*PBT + ncb*2;

    uint32_t aAo = (uint32_t)((warp_m*64 + (lid & 7) + ((lid >> 3) & 1)*8)*80 + ((lid >> 4) & 1)*16);
    uint32_t aBo = (uint32_t)(((lid & 7) + ((lid >> 3) & 1)*8)*PBT + warp_n*64 + ((lid >> 4) & 1)*16);

    float acc[4][4][4] = {};

    uint4 rA0, rA1;
    uint2 rAt[4], rCv[4];
    float rGc;
    #define PROJ_LOAD(kc_) do{ \
        int c0_ = (kc_) * 32; \
        rA0 = *(const uint4*)(pah + c0_*2); \
        rA1 = *(const uint4*)(pah + c0_*2 + 16); \
        rGc = g_gc[bb*Cc + c0_ + cr]; \
        const uint2* at_ = (const uint2*)(At + (size_t)(c0_ + cr) * Nn); \
        const uint2* cv_ = (const uint2*)(Cv + (size_t)(c0_ + cr) * Nn); \
        rAt[0] = at_[0]; rAt[1] = at_[1]; rAt[2] = at_[2]; rAt[3] = at_[3]; \
        rCv[0] = cv_[0]; rCv[1] = cv_[1]; rCv[2] = cv_[2]; rCv[3] = cv_[3]; \
    } while(0)

    PROJ_LOAD(0);

    #pragma unroll 1
    for (int kc = 0; kc < 8; kc++){
        *(uint4*)(dA + PAH)      = rA0;
        *(uint4*)(dA + PAH + 16) = rA1;
        {
            uint32_t o[8];
            #pragma unroll
            for (int jj = 0; jj < 4; jj++){
                __half2 a0 = *(__half2*)&rAt[jj].x, a1 = *(__half2*)&rAt[jj].y;
                __half2 c0h = *(__half2*)&rCv[jj].x, c1h = *(__half2*)&rCv[jj].y;
                float2 a = __half22float2(a0), c = __half22float2(c0h);
                float2 a2 = __half22float2(a1), c2 = __half22float2(c1h);
                float v0 = a.x*gsa[jj*4]   + c.x*rGc;
                float v1 = a.y*gsa[jj*4+1] + c.y*rGc;
                float v2 = a2.x*gsa[jj*4+2] + c2.x*rGc;
                float v3 = a2.y*gsa[jj*4+3] + c2.y*rGc;
                o[jj*2]   = pack_h2(__float2half(v0), __float2half(v1));
                o[jj*2+1] = pack_h2(__float2half(v2), __float2half(v3));
            }
            *(uint4*)(dB)      = make_uint4(o[0], o[1], o[2], o[3]);
            *(uint4*)(dB + 16) = make_uint4(o[4], o[5], o[6], o[7]);
        }
        __syncthreads();
        if (kc < 7) PROJ_LOAD(kc + 1);
        #pragma unroll
        for (int ks = 0; ks < 2; ks++){
            uint32_t kro = (uint32_t)(ks*16)*PBT;
            uint32_t bh[8], arh[4];
            ldmx4t(bh,     sb + PBH + aBo + kro);
            ldmx4t(bh + 4, sb + PBH + aBo + kro + 32);
            uint32_t kofs = ks*32;
            #pragma unroll
            for (int mi = 0; mi < 4; mi++){
                ldmx4(arh, sb + PAH + aAo + kofs + (uint32_t)(mi*16)*80);
                #pragma unroll
                for (int ni = 0; ni < 4; ni++) mma_f16(acc[mi][ni], arh, bh[ni*2], bh[ni*2+1]);
            }
        }
        __syncthreads();
    }

    int gid = lid >> 2, q4 = lid & 3;
    int obase = cblk + warp_m*64 + gid;
    #pragma unroll
    for (int mi = 0; mi < 4; mi++){
        int o0 = obase + mi*16;
        float bo0 = bias[o0], bo1 = bias[o0 + 8];
        float* r0 = out + ((size_t)(bb*Cc + o0)) * Nn;
        float* r1 = out + ((size_t)(bb*Cc + o0 + 8)) * Nn;
        #pragma unroll
        for (int ni = 0; ni < 4; ni++){
            int n = n0 + warp_n*32 + ni*8 + q4*2;
            *(float2*)&r0[n] = make_float2(acc[mi][ni][0] + bo0, acc[mi][ni][1] + bo0);
            *(float2*)&r1[n] = make_float2(acc[mi][ni][2] + bo1, acc[mi][ni][3] + bo1);
        }
    }
}

// =================================================================================
extern "C" void kernel_launch(void* const* d_in, const int* in_sizes, int n_in,
                              void* d_out, int out_size){
    const float* x     = (const float*)d_in[0];
    const float* ln_g  = (const float*)d_in[1];
    const float* ln_b  = (const float*)d_in[2];
    const float* w_qkv = (const float*)d_in[3];
    const float* w_q   = (const float*)d_in[4];
    const float* b_q   = (const float*)d_in[5];
    const float* temp  = (const float*)d_in[6];
    const float* dw_w  = (const float*)d_in[7];
    const float* dw_b  = (const float*)d_in[8];
    const float* ci_w1 = (const float*)d_in[9];
    const float* ci_b1 = (const float*)d_in[10];
    const float* ci_w2 = (const float*)d_in[11];
    const float* ci_b2 = (const float*)d_in[12];
    const float* si_w1 = (const float*)d_in[13];
    const float* si_b1 = (const float*)d_in[14];
    const float* si_w2 = (const float*)d_in[15];
    const float* si_b2 = (const float*)d_in[16];
    const float* pj_w  = (const float*)d_in[17];
    const float* pj_b  = (const float*)d_in[18];
    float* out = (float*)d_out;

    cudaFuncSetAttribute(k_qkv_mma, cudaFuncAttributeMaxDynamicSharedMemorySize, QKV_SMEM);

    k_zero<<<512, 256>>>();
    k_layernorm<<<Bq*(Nn/32), 256>>>(x, ln_g, ln_b);
    k_buildWP<<<320, 256>>>(w_qkv, w_q, pj_w);
    k_qkv_mma<<<dim3(6, BN/128), 256, QKV_SMEM>>>(b_q);
    k_attn_qk_mma<<<dim3(8, Bq*NH), 256>>>();
    k_attn_v_mma<<<dim3(Nn/128, Bq*NH), 256>>>(temp);
    k_dwconv<<<Bq*Cc, 256>>>(dw_w, dw_b);
    k_spatial<<<Bq*16, 256>>>(si_w1, si_b1, si_w2, si_b2);
    k_channel_mlp<<<Bq, 256>>>(ci_w1, ci_b1, ci_w2, ci_b2);
    k_proj_mma<<<dim3(2, BN/128), 256>>>(pj_b, out);
}